// round 13
// baseline (speedup 1.0000x reference)
#include <cuda_runtime.h>
#include <cstdint>

// Problem constants
#define QB   64
#define QH   8
#define QM   1024
#define QC   128
#define QMID 64
#define NTHREADS 256

__device__ __forceinline__ void ffma2(unsigned long long &d, unsigned long long a, unsigned long long b) {
    asm volatile("fma.rn.f32x2 %0, %1, %2, %0;" : "+l"(d) : "l"(a), "l"(b));
}
__device__ __forceinline__ unsigned long long splat2(float v) {
    unsigned long long r;
    asm("mov.b64 %0, {%1, %1};" : "=l"(r) : "f"(v));
    return r;
}
__device__ __forceinline__ float2 unpack2(unsigned long long v) {
    float2 r;
    asm("mov.b64 {%0, %1}, %2;" : "=f"(r.x), "=f"(r.y) : "l"(v));
    return r;
}
static __device__ __forceinline__ uint32_t smem_u32(const void* p) {
    uint32_t a;
    asm("{ .reg .u64 t; cvta.to.shared.u64 t, %1; cvt.u32.u64 %0, t; }" : "=r"(a) : "l"(p));
    return a;
}
static __device__ __forceinline__ void cp_async16(uint32_t dst, const void* src) {
    asm volatile("cp.async.cg.shared.global [%0], [%1], 16;" :: "r"(dst), "l"(src) : "memory");
}
#define CP_COMMIT() asm volatile("cp.async.commit_group;" ::: "memory")
#define CP_WAIT0()  asm volatile("cp.async.wait_group 0;" ::: "memory")
#define CP_WAIT1()  asm volatile("cp.async.wait_group 1;" ::: "memory")

// dynamic smem layout (floats):
//  wq      : 128*64 = 8192   (phase2: partial buffer 8x128)
//  bufs    : 8 warps * 2 * 8*128 = 16384   (per-warp double buffers)
//  logit   : 1024
//  midx    : 1024 (ints)
//  wl/bb/pool : 64*3
//  red     : 128  (q staging, then unused)
//  sc      : 48
#define SMEM_FLOATS (8192 + 16384 + 1024 + 1024 + 64 + 64 + 64 + 128 + 48)

extern "C" __global__ void __launch_bounds__(NTHREADS, 2)
scatt_kernel(const float* __restrict__ query,
             const float* __restrict__ key_feat,
             const int*   __restrict__ att_mask,
             const float* __restrict__ value1,
             const float* __restrict__ value2,
             const float* __restrict__ w_basic,
             const float* __restrict__ b_basic,
             const float* __restrict__ w_last,
             const float* __restrict__ b_last,
             const float* __restrict__ w_last2,
             const float* __restrict__ b_last2,
             float* __restrict__ out)
{
    extern __shared__ float sm[];
    float* wq_s    = sm;                      // [k][o]  k:128 o:64
    float* bufs_s  = wq_s + 8192;             // 8 warps x 2048 floats
    float* logit_s = bufs_s + 16384;          // 1024 (compact e values)
    int*   midx_s  = (int*)(logit_s + 1024);  // 1024 compact row indices
    float* wl_s    = (float*)(midx_s + 1024); // 64
    float* bb_s    = wl_s + 64;               // 64
    float* pool_s  = bb_s + 64;               // 64
    float* red_s   = pool_s + 64;             // 128 (q staging)
    float* sc_s    = red_s + 128;             // 48
    int*   wtot_i  = (int*)(sc_s + 36);       // 8 warp totals

    const int tid = threadIdx.x;
    const int wid = tid >> 5;
    const int lid = tid & 31;
    const int bh  = blockIdx.x;
    const int b   = bh >> 3;
    const int h   = bh & 7;

    const float* qp  = query    + bh * QC;
    const float* kfp = key_feat + (size_t)bh * QM * QC;

    // ---------------- mask compaction (prefix scan over 1024 rows) ----------
    midx_s[tid] = 0; midx_s[tid + 256] = 0; midx_s[tid + 512] = 0; midx_s[tid + 768] = 0;

    int mvbits = 0, cnt = 0;
    #pragma unroll
    for (int j = 0; j < 4; ++j) {
        int mv = att_mask[b * QM + (tid << 2) + j];
        mvbits |= mv << j;
        cnt += mv;
    }
    int inc = cnt;
    #pragma unroll
    for (int o = 1; o < 32; o <<= 1) {
        int n = __shfl_up_sync(~0u, inc, o);
        if (lid >= o) inc += n;
    }
    if (lid == 31) wtot_i[wid] = inc;
    __syncthreads();
    int base = 0, nact = 0;
    #pragma unroll
    for (int w = 0; w < 8; ++w) {
        int t8 = wtot_i[w];
        if (w < wid) base += t8;
        nact += t8;
    }
    int pos = base + (inc - cnt);
    __syncthreads();
    #pragma unroll
    for (int j = 0; j < 4; ++j) {
        if ((mvbits >> j) & 1) midx_s[pos++] = (tid << 2) + j;
    }

    const int nblk = (nact + 7) >> 3;     // 8-row blocks

    if (tid < 64) {
        pool_s[tid] = 0.f;
        wl_s[tid]   = w_last[h * QMID + tid];
        bb_s[tid]   = b_basic[h * QMID + tid];
    }
    for (int i = tid; i < QC; i += NTHREADS) red_s[i] = qp[i];
    __syncthreads();   // midx ready for staging; q staged

    // per-warp double buffers (each 1024 floats = 8 rows x 128)
    float* buf0 = bufs_s + wid * 2048;
    float* buf1 = buf0 + 1024;
    const uint32_t buf_addr[2] = { smem_u32(buf0), smem_u32(buf1) };

    // lane roles: stage: row = lid>>2, chunk-col = lid&3; gemm: r = lid>>4, c = lid&15
    const int srow = lid >> 2;
    const int scol = lid & 3;
    const int r    = lid >> 4;
    const int c    = lid & 15;

    // stage block BI (8 gathered rows x 512B) into buffer
    // row stride = 512 BYTES (srow << 9); swizzle k4' = k4 ^ row(low3)
    #define STAGE_BLOCK(BI, BUFA)                                                  \
        {                                                                          \
            const float* _src = kfp + ((size_t)midx_s[((BI) << 3) + srow] << 7)    \
                                + (scol << 5);                                     \
            const uint32_t _dst = (BUFA) + (uint32_t)(srow << 9);                  \
            _Pragma("unroll")                                                      \
            for (int _i = 0; _i < 8; ++_i) {                                       \
                int _k4 = (scol << 3) + (_i ^ srow);                               \
                cp_async16(_dst + (uint32_t)(_k4 << 4), _src + (_i << 2));         \
            }                                                                      \
            CP_COMMIT();                                                           \
        }

    // prefetch this warp's first two blocks (overlaps wq build)
    if (wid < nblk) STAGE_BLOCK(wid, buf_addr[0]);
    if (wid + 8 < nblk) STAGE_BLOCK(wid + 8, buf_addr[1]);

    // wq[k][o] = q[k] * w_basic[h][k][o]
    for (int i = tid; i < QC * QMID; i += NTHREADS) {
        int k = i >> 6;
        wq_s[i] = red_s[k] * w_basic[(h * QC + k) * QMID + (i & 63)];
    }
    __syncthreads();   // wq ready

    float bb4[4], wl4[4];
    #pragma unroll
    for (int j = 0; j < 4; ++j) {
        bb4[j] = bb_s[(c << 2) + j];
        wl4[j] = wl_s[(c << 2) + j];
    }
    float pp[4] = {0.f, 0.f, 0.f, 0.f};
    float se_p  = 0.f;

    const float* wb = wq_s + (c << 2);

    // ---------------- warp-autonomous mainloop (no block barriers) ----------
    int ib = 0;
    for (int bi = wid; bi < nblk; bi += 8, ++ib) {
        if (bi + 8 < nblk) { CP_WAIT1(); } else { CP_WAIT0(); }
        __syncwarp();

        const float* buf = ib & 1 ? buf1 : buf0;

        // GEMM: 4 rows (r, r+2, r+4, r+6) x 4 cols (4c..4c+3), k = 128
        unsigned long long acc[4][2];
        #pragma unroll
        for (int j = 0; j < 4; ++j) { acc[j][0] = 0ULL; acc[j][1] = 0ULL; }

        #pragma unroll 4
        for (int k4 = 0; k4 < 32; ++k4) {
            float4 a[4];
            #pragma unroll
            for (int j = 0; j < 4; ++j) {
                const int rr = r + (j << 1);
                a[j] = *(const float4*)(buf + (rr << 7) + ((k4 ^ rr) << 2));
            }
            ulonglong2 bv[4];
            #pragma unroll
            for (int t = 0; t < 4; ++t)
                bv[t] = *(const ulonglong2*)(wb + (((k4 << 2) + t) << 6));

            #pragma unroll
            for (int t = 0; t < 4; ++t) {
                #pragma unroll
                for (int j = 0; j < 4; ++j) {
                    float av = (t == 0) ? a[j].x : (t == 1) ? a[j].y : (t == 2) ? a[j].z : a[j].w;
                    unsigned long long ap = splat2(av);
                    ffma2(acc[j][0], ap, bv[t].x);
                    ffma2(acc[j][1], ap, bv[t].y);
                }
            }
        }

        __syncwarp();   // all lanes done reading buf before restage
        if (bi + 16 < nblk) STAGE_BLOCK(bi + 16, buf_addr[ib & 1]);

        // register epilogue: relu+bias, pool, logit -> e (no-max softmax)
        #pragma unroll
        for (int j = 0; j < 4; ++j) {
            const int row = r + (j << 1);
            const int mg  = (bi << 3) + row;
            const float vld = (mg < nact) ? 1.f : 0.f;
            float2 lo = unpack2(acc[j][0]);
            float2 hi = unpack2(acc[j][1]);
            float x0 = fmaxf(lo.x + bb4[0], 0.f);
            float x1 = fmaxf(lo.y + bb4[1], 0.f);
            float x2 = fmaxf(hi.x + bb4[2], 0.f);
            float x3 = fmaxf(hi.y + bb4[3], 0.f);
            pp[0] += x0 * vld; pp[1] += x1 * vld; pp[2] += x2 * vld; pp[3] += x3 * vld;
            float lp = x0 * wl4[0] + x1 * wl4[1] + x2 * wl4[2] + x3 * wl4[3];
            lp += __shfl_xor_sync(~0u, lp, 1);
            lp += __shfl_xor_sync(~0u, lp, 2);
            lp += __shfl_xor_sync(~0u, lp, 4);
            lp += __shfl_xor_sync(~0u, lp, 8);
            float e = __expf(lp) * vld;
            if (c == 0) { logit_s[mg] = e; se_p += e; }
        }
    }

    // ---------------- reductions: pool + se ----------------
    #pragma unroll
    for (int j = 0; j < 4; ++j) {
        float v = pp[j];
        v += __shfl_xor_sync(~0u, v, 16);
        if (lid < 16) atomicAdd(&pool_s[(c << 2) + j], v);
    }
    {
        float v = se_p;   // nonzero only on c==0 lanes (lid 0 and 16)
        v += __shfl_xor_sync(~0u, v, 16);
        if (lid == 0) sc_s[wid] = v;
    }
    __syncthreads();   // logits + pool + se partials complete
    if (tid == 0) {
        float v = 0.f;
        #pragma unroll
        for (int w = 0; w < 8; ++w) v += sc_s[w];
        sc_s[33] = 1.0f / v;
    }
    __syncthreads();
    const float inv_se  = sc_s[33];
    const float cnt_inv = 1.0f / (float)nact;

    // ---------------- v2 = alpha^T @ value2 over ACTIVE rows only ------------
    {
        const int qc    = tid & 31;
        const int slice = tid >> 5;
        const float* vbase = value2 + (size_t)bh * QM * QC + (qc << 2);
        float ax = 0.f, ay = 0.f, az = 0.f, aw = 0.f;
        #pragma unroll 4
        for (int i = slice; i < nact; i += 8) {
            float a4 = logit_s[i];
            int msrc = midx_s[i];
            float4 v = __ldcs((const float4*)(vbase + ((size_t)msrc << 7)));
            ax += a4 * v.x; ay += a4 * v.y; az += a4 * v.z; aw += a4 * v.w;
        }
        *(float4*)(wq_s + slice * QC + (qc << 2)) = make_float4(ax, ay, az, aw);
    }
    __syncthreads();

    // ---------------- final reduce + channel gate + output ----------------
    if (tid < QC) {
        const int d = tid;
        float v2v = 0.f;
        #pragma unroll
        for (int s = 0; s < 8; ++s) v2v += wq_s[s * QC + d];
        v2v *= inv_se;

        const float* w2 = w_last2 + (h * QMID) * QC + d;
        float pv = 0.f;
        #pragma unroll 8
        for (int o = 0; o < QMID; ++o) pv += (pool_s[o] * cnt_inv) * w2[o * QC];
        float z   = pv + b_last2[h * QC + d];
        float acv = 1.0f / (1.0f + __expf(-z));
        out[bh * QC + d] = value1[bh * QC + d] * v2v * acv;
    }
}

extern "C" void kernel_launch(void* const* d_in, const int* in_sizes, int n_in,
                              void* d_out, int out_size) {
    const float* query    = (const float*)d_in[0];
    const float* key_feat = (const float*)d_in[1];
    const int*   att_mask = (const int*)  d_in[2];
    const float* value1   = (const float*)d_in[3];
    const float* value2   = (const float*)d_in[4];
    const float* w_basic  = (const float*)d_in[5];
    const float* b_basic  = (const float*)d_in[6];
    const float* w_last   = (const float*)d_in[7];
    const float* b_last   = (const float*)d_in[8];
    const float* w_last2  = (const float*)d_in[9];
    const float* b_last2  = (const float*)d_in[10];
    float* out = (float*)d_out;

    const int smem_bytes = SMEM_FLOATS * (int)sizeof(float);
    cudaFuncSetAttribute(scatt_kernel, cudaFuncAttributeMaxDynamicSharedMemorySize, smem_bytes);
    scatt_kernel<<<QB * QH, NTHREADS, smem_bytes>>>(
        query, key_feat, att_mask, value1, value2,
        w_basic, b_basic, w_last, b_last, w_last2, b_last2, out);
}

// round 14
// speedup vs baseline: 1.0665x; 1.0665x over previous
#include <cuda_runtime.h>
#include <cstdint>

// Problem constants
#define QB   64
#define QH   8
#define QM   1024
#define QC   128
#define QMID 64
#define TM   64                   // rows per tile (one tile per group in flight)
#define NTHREADS 256

__device__ __forceinline__ void ffma2(unsigned long long &d, unsigned long long a, unsigned long long b) {
    asm volatile("fma.rn.f32x2 %0, %1, %2, %0;" : "+l"(d) : "l"(a), "l"(b));
}
__device__ __forceinline__ unsigned long long splat2(float v) {
    unsigned long long r;
    asm("mov.b64 %0, {%1, %1};" : "=l"(r) : "f"(v));
    return r;
}
__device__ __forceinline__ float2 unpack2(unsigned long long v) {
    float2 r;
    asm("mov.b64 {%0, %1}, %2;" : "=f"(r.x), "=f"(r.y) : "l"(v));
    return r;
}
static __device__ __forceinline__ uint32_t smem_u32(const void* p) {
    uint32_t a;
    asm("{ .reg .u64 t; cvta.to.shared.u64 t, %1; cvt.u32.u64 %0, t; }" : "=r"(a) : "l"(p));
    return a;
}
static __device__ __forceinline__ void cp_async16(uint32_t dst, const void* src) {
    asm volatile("cp.async.cg.shared.global [%0], [%1], 16;" :: "r"(dst), "l"(src) : "memory");
}
#define CP_COMMIT() asm volatile("cp.async.commit_group;" ::: "memory")
#define CP_WAIT0()  asm volatile("cp.async.wait_group 0;" ::: "memory")
#define BAR_GROUP(ID) asm volatile("bar.sync %0, 128;" :: "r"(ID) : "memory")

// dynamic smem layout (floats):
//  wq      : 128*64 = 8192   (phase2: partial buffer 8x128)
//  kf0/kf1 : 2 * 64*128 = 16384   (one per group)
//  logit   : 1024  (stores e values)
//  midx    : 1024 (ints)
//  wl/bb/pool : 64*3
//  red     : 128
//  sc      : 48
#define SMEM_FLOATS (8192 + 16384 + 1024 + 1024 + 64 + 64 + 64 + 128 + 48)

extern "C" __global__ void __launch_bounds__(NTHREADS, 2)
scatt_kernel(const float* __restrict__ query,
             const float* __restrict__ key_feat,
             const int*   __restrict__ att_mask,
             const float* __restrict__ value1,
             const float* __restrict__ value2,
             const float* __restrict__ w_basic,
             const float* __restrict__ b_basic,
             const float* __restrict__ w_last,
             const float* __restrict__ b_last,
             const float* __restrict__ w_last2,
             const float* __restrict__ b_last2,
             float* __restrict__ out)
{
    extern __shared__ float sm[];
    float* wq_s    = sm;                      // [k][o]  k:128 o:64
    float* kf0_s   = wq_s + 8192;             // group-0 buffer: 64x128 quad-swizzled
    float* kf1_s   = kf0_s + 8192;            // group-1 buffer
    float* logit_s = kf1_s + 8192;            // 1024 (e values, compact)
    int*   midx_s  = (int*)(logit_s + 1024);  // 1024 compact row indices
    float* wl_s    = (float*)(midx_s + 1024); // 64
    float* bb_s    = wl_s + 64;               // 64
    float* pool_s  = bb_s + 64;               // 64
    float* red_s   = pool_s + 64;             // 128 (q staging)
    float* sc_s    = red_s + 128;             // 48
    int*   wtot_i  = (int*)(sc_s + 36);       // 8 warp totals

    const int tid = threadIdx.x;
    const int wid = tid >> 5;
    const int lid = tid & 31;
    const int bh  = blockIdx.x;
    const int b   = bh >> 3;
    const int h   = bh & 7;

    const float* qp  = query    + bh * QC;
    const float* kfp = key_feat + (size_t)bh * QM * QC;

    // ---------------- mask compaction (prefix scan over 1024 rows) ----------
    int mvbits = 0, cnt = 0;
    #pragma unroll
    for (int j = 0; j < 4; ++j) {
        int mv = att_mask[b * QM + (tid << 2) + j];
        mvbits |= mv << j;
        cnt += mv;
    }
    int inc = cnt;
    #pragma unroll
    for (int o = 1; o < 32; o <<= 1) {
        int n = __shfl_up_sync(~0u, inc, o);
        if (lid >= o) inc += n;
    }
    if (lid == 31) wtot_i[wid] = inc;
    __syncthreads();
    int base = 0, nact = 0;
    #pragma unroll
    for (int w = 0; w < 8; ++w) {
        int t8 = wtot_i[w];
        if (w < wid) base += t8;
        nact += t8;
    }
    int pos = base + (inc - cnt);
    #pragma unroll
    for (int j = 0; j < 4; ++j) {
        if ((mvbits >> j) & 1) midx_s[pos++] = (tid << 2) + j;
    }

    const int ntiles = (nact + TM - 1) >> 6;
    const int nlast  = nact - 1;

    if (tid < 64) {
        pool_s[tid] = 0.f;
        wl_s[tid]   = w_last[h * QMID + tid];
        bb_s[tid]   = b_basic[h * QMID + tid];
    }
    for (int i = tid; i < QC; i += NTHREADS) red_s[i] = qp[i];
    __syncthreads();   // midx ready for staging; q staged

    // group decomposition
    const int g   = tid >> 7;         // 0 or 1
    const int gt  = tid & 127;        // thread within group
    const int rg  = gt >> 4;          // 0..7 -> rows rg*8..rg*8+7
    const int cg  = gt & 15;          // 0..15 -> cols cg*4..cg*4+3
    const uint32_t mybuf_addr = smem_u32(g ? kf1_s : kf0_s);
    const float*   mybuf      = g ? kf1_s : kf0_s;
    const int      barid      = 1 + g;

    // stage one gathered 64-row tile (clamped index for pad rows)
    #define STAGE_TILE_G(TILE)                                                     \
        {                                                                          \
            const int _t0 = (TILE) * TM;                                           \
            _Pragma("unroll")                                                      \
            for (int _it = 0; _it < 16; ++_it) {                                   \
                int _f  = gt + _it * 128;                                          \
                int _m  = _f >> 5;                                                 \
                int _qk = _f & 31;                                                 \
                int _qs = _qk ^ ((_m >> 2) & 7);                                   \
                int _sl = _t0 + _m; if (_sl > nlast) _sl = nlast;                  \
                int _src_row = midx_s[_sl];                                        \
                cp_async16(mybuf_addr + (uint32_t)(((_m << 7) + (_qs << 2)) << 2), \
                           kfp + ((size_t)_src_row << 7) + (_qk << 2));            \
            }                                                                      \
            CP_COMMIT();                                                           \
        }

    // each group prefetches its first tile (overlaps wq build)
    if (g < ntiles) STAGE_TILE_G(g);

    // wq[k][o] = q[k] * w_basic[h][k][o]
    for (int i = tid; i < QC * QMID; i += NTHREADS) {
        int k = i >> 6;
        wq_s[i] = red_s[k] * w_basic[(h * QC + k) * QMID + (i & 63)];
    }
    __syncthreads();   // wq ready

    float bb4[4], wl4[4];
    #pragma unroll
    for (int j = 0; j < 4; ++j) {
        bb4[j] = bb_s[(cg << 2) + j];
        wl4[j] = wl_s[(cg << 2) + j];
    }
    float pp[4] = {0.f, 0.f, 0.f, 0.f};
    float se_p  = 0.f;

    const float* wb  = wq_s + (cg << 2);
    const float* kfb = mybuf + (rg << 10);    // rg*8 rows * 128

    // ---------------- main tiles: group g handles tiles g, g+2, ... ----------
    for (int tile = g; tile < ntiles; tile += 2) {
        CP_WAIT0();
        BAR_GROUP(barid);

        // full-k GEMM: 8 rows x 4 cols per thread, 32 k-quads
        unsigned long long acc[8][2];
        #pragma unroll
        for (int r = 0; r < 8; ++r) { acc[r][0] = 0ULL; acc[r][1] = 0ULL; }

        #pragma unroll 2
        for (int qq = 0; qq < 32; ++qq) {
            ulonglong2 bv[4];
            #pragma unroll
            for (int j = 0; j < 4; ++j)
                bv[j] = *(const ulonglong2*)(wb + ((qq << 2) + j) * QMID);

            #pragma unroll
            for (int half = 0; half < 2; ++half) {
                const int qs4 = ((qq ^ (((rg << 1) + half) & 7)) << 2);
                float4 a[4];
                #pragma unroll
                for (int r = 0; r < 4; ++r)
                    a[r] = *(const float4*)(kfb + (((half << 2) + r) << 7) + qs4);

                #pragma unroll
                for (int j = 0; j < 4; ++j) {
                    #pragma unroll
                    for (int r = 0; r < 4; ++r) {
                        float av = (j == 0) ? a[r].x : (j == 1) ? a[r].y : (j == 2) ? a[r].z : a[r].w;
                        unsigned long long ap = splat2(av);
                        const int rr = (half << 2) + r;
                        ffma2(acc[rr][0], ap, bv[j].x);
                        ffma2(acc[rr][1], ap, bv[j].y);
                    }
                }
            }
        }

        BAR_GROUP(barid);   // group's reads of its buffer done

        // issue staging for this group's next tile (overlaps epilogue)
        if (tile + 2 < ntiles) STAGE_TILE_G(tile + 2);

        // register epilogue: relu+bias, pool, logit -> e (no-max softmax)
        #pragma unroll
        for (int r = 0; r < 8; ++r) {
            const int mg = tile * TM + (rg << 3) + r;
            const float vld = (mg < nact) ? 1.f : 0.f;
            float2 lo = unpack2(acc[r][0]);
            float2 hi = unpack2(acc[r][1]);
            float x0 = fmaxf(lo.x + bb4[0], 0.f);
            float x1 = fmaxf(lo.y + bb4[1], 0.f);
            float x2 = fmaxf(hi.x + bb4[2], 0.f);
            float x3 = fmaxf(hi.y + bb4[3], 0.f);
            pp[0] += x0 * vld; pp[1] += x1 * vld; pp[2] += x2 * vld; pp[3] += x3 * vld;
            float lp = x0 * wl4[0] + x1 * wl4[1] + x2 * wl4[2] + x3 * wl4[3];
            lp += __shfl_xor_sync(~0u, lp, 1);
            lp += __shfl_xor_sync(~0u, lp, 2);
            lp += __shfl_xor_sync(~0u, lp, 4);
            lp += __shfl_xor_sync(~0u, lp, 8);
            float e = __expf(lp) * vld;
            if (cg == 0) { if (mg < nact) logit_s[mg] = e; se_p += e; }
        }
    }

    // ---------------- reductions: pool + se ----------------
    #pragma unroll
    for (int j = 0; j < 4; ++j) {
        float v = pp[j];
        v += __shfl_xor_sync(~0u, v, 16);
        if (lid < 16) atomicAdd(&pool_s[(cg << 2) + j], v);
    }
    {
        float v = se_p;   // nonzero only on cg==0 lanes (lid 0 and 16)
        v += __shfl_xor_sync(~0u, v, 16);
        if (lid == 0) sc_s[wid] = v;
        else if (lid == 16) sc_s[8 + wid] = 0.f;   // ensure defined slots? no-op
    }
    __syncthreads();   // e values + pool + se partials complete
    if (tid == 0) {
        float v = 0.f;
        #pragma unroll
        for (int w = 0; w < 8; ++w) v += sc_s[w];
        sc_s[33] = 1.0f / v;
    }
    __syncthreads();
    const float inv_se  = sc_s[33];
    const float cnt_inv = 1.0f / (float)nact;

    // ---------------- v2 = alpha^T @ value2 over ACTIVE rows only ------------
    {
        const int qc    = tid & 31;
        const int slice = tid >> 5;
        const float* vbase = value2 + (size_t)bh * QM * QC + (qc << 2);
        float ax = 0.f, ay = 0.f, az = 0.f, aw = 0.f;
        #pragma unroll 8
        for (int i = slice; i < nact; i += 8) {
            float a4 = logit_s[i];
            int msrc = midx_s[i];
            float4 v = __ldcs((const float4*)(vbase + ((size_t)msrc << 7)));
            ax += a4 * v.x; ay += a4 * v.y; az += a4 * v.z; aw += a4 * v.w;
        }
        *(float4*)(wq_s + slice * QC + (qc << 2)) = make_float4(ax, ay, az, aw);
    }
    __syncthreads();

    // ---------------- final reduce + channel gate + output ----------------
    if (tid < QC) {
        const int d = tid;
        float v2v = 0.f;
        #pragma unroll
        for (int s = 0; s < 8; ++s) v2v += wq_s[s * QC + d];
        v2v *= inv_se;

        const float* w2 = w_last2 + (h * QMID) * QC + d;
        float pv = 0.f;
        #pragma unroll 8
        for (int o = 0; o < QMID; ++o) pv += (pool_s[o] * cnt_inv) * w2[o * QC];
        float z   = pv + b_last2[h * QC + d];
        float acv = 1.0f / (1.0f + __expf(-z));
        out[bh * QC + d] = value1[bh * QC + d] * v2v * acv;
    }
}

extern "C" void kernel_launch(void* const* d_in, const int* in_sizes, int n_in,
                              void* d_out, int out_size) {
    const float* query    = (const float*)d_in[0];
    const float* key_feat = (const float*)d_in[1];
    const int*   att_mask = (const int*)  d_in[2];
    const float* value1   = (const float*)d_in[3];
    const float* value2   = (const float*)d_in[4];
    const float* w_basic  = (const float*)d_in[5];
    const float* b_basic  = (const float*)d_in[6];
    const float* w_last   = (const float*)d_in[7];
    const float* b_last   = (const float*)d_in[8];
    const float* w_last2  = (const float*)d_in[9];
    const float* b_last2  = (const float*)d_in[10];
    float* out = (float*)d_out;

    const int smem_bytes = SMEM_FLOATS * (int)sizeof(float);
    cudaFuncSetAttribute(scatt_kernel, cudaFuncAttributeMaxDynamicSharedMemorySize, smem_bytes);
    scatt_kernel<<<QB * QH, NTHREADS, smem_bytes>>>(
        query, key_feat, att_mask, value1, value2,
        w_basic, b_basic, w_last, b_last, w_last2, b_last2, out);
}

// round 15
// speedup vs baseline: 1.0833x; 1.0158x over previous
#include <cuda_runtime.h>
#include <cstdint>

// Problem constants
#define QB   64
#define QH   8
#define QM   1024
#define QC   128
#define QMID 64
#define TM   32                   // rows per tile (one per group in flight)
#define NTHREADS 256

__device__ __forceinline__ void ffma2(unsigned long long &d, unsigned long long a, unsigned long long b) {
    asm volatile("fma.rn.f32x2 %0, %1, %2, %0;" : "+l"(d) : "l"(a), "l"(b));
}
__device__ __forceinline__ unsigned long long splat2(float v) {
    unsigned long long r;
    asm("mov.b64 %0, {%1, %1};" : "=l"(r) : "f"(v));
    return r;
}
__device__ __forceinline__ float2 unpack2(unsigned long long v) {
    float2 r;
    asm("mov.b64 {%0, %1}, %2;" : "=f"(r.x), "=f"(r.y) : "l"(v));
    return r;
}
static __device__ __forceinline__ uint32_t smem_u32(const void* p) {
    uint32_t a;
    asm("{ .reg .u64 t; cvta.to.shared.u64 t, %1; cvt.u32.u64 %0, t; }" : "=r"(a) : "l"(p));
    return a;
}
static __device__ __forceinline__ void cp_async16(uint32_t dst, const void* src) {
    asm volatile("cp.async.cg.shared.global [%0], [%1], 16;" :: "r"(dst), "l"(src) : "memory");
}
#define CP_COMMIT() asm volatile("cp.async.commit_group;" ::: "memory")
#define CP_WAIT0()  asm volatile("cp.async.wait_group 0;" ::: "memory")
#define BAR_GROUP(ID) asm volatile("bar.sync %0, 128;" :: "r"(ID) : "memory")

// dynamic smem layout (floats):
//  wq      : 128*64 = 8192   (phase2: partial buffer 8x128)
//  kf0/kf1 : 2 * 32*128 = 8192   (one 16KB buffer per group)
//  logit   : 1024  (e values)
//  midx    : 1024 (ints)
//  wl/bb/pool : 64*3
//  red     : 128
//  sc      : 48
// total = 18800 floats = 75200 B  -> 3 CTAs/SM fit in 228KB
#define SMEM_FLOATS (8192 + 8192 + 1024 + 1024 + 64 + 64 + 64 + 128 + 48)

extern "C" __global__ void __launch_bounds__(NTHREADS, 3)
scatt_kernel(const float* __restrict__ query,
             const float* __restrict__ key_feat,
             const int*   __restrict__ att_mask,
             const float* __restrict__ value1,
             const float* __restrict__ value2,
             const float* __restrict__ w_basic,
             const float* __restrict__ b_basic,
             const float* __restrict__ w_last,
             const float* __restrict__ b_last,
             const float* __restrict__ w_last2,
             const float* __restrict__ b_last2,
             float* __restrict__ out)
{
    extern __shared__ float sm[];
    float* wq_s    = sm;                      // [k][o]  k:128 o:64
    float* kf0_s   = wq_s + 8192;             // group-0 buffer: 32x128 quad-swizzled
    float* kf1_s   = kf0_s + 4096;            // group-1 buffer
    float* logit_s = kf1_s + 4096;            // 1024 (e values, compact)
    int*   midx_s  = (int*)(logit_s + 1024);  // 1024 compact row indices
    float* wl_s    = (float*)(midx_s + 1024); // 64
    float* bb_s    = wl_s + 64;               // 64
    float* pool_s  = bb_s + 64;               // 64
    float* red_s   = pool_s + 64;             // 128 (q staging)
    float* sc_s    = red_s + 128;             // 48
    int*   wtot_i  = (int*)(sc_s + 36);       // 8 warp totals

    const int tid = threadIdx.x;
    const int wid = tid >> 5;
    const int lid = tid & 31;
    const int bh  = blockIdx.x;
    const int b   = bh >> 3;
    const int h   = bh & 7;

    const float* qp  = query    + bh * QC;
    const float* kfp = key_feat + (size_t)bh * QM * QC;

    // ---------------- mask compaction (prefix scan over 1024 rows) ----------
    int mvbits = 0, cnt = 0;
    #pragma unroll
    for (int j = 0; j < 4; ++j) {
        int mv = att_mask[b * QM + (tid << 2) + j];
        mvbits |= mv << j;
        cnt += mv;
    }
    int inc = cnt;
    #pragma unroll
    for (int o = 1; o < 32; o <<= 1) {
        int n = __shfl_up_sync(~0u, inc, o);
        if (lid >= o) inc += n;
    }
    if (lid == 31) wtot_i[wid] = inc;
    __syncthreads();
    int base = 0, nact = 0;
    #pragma unroll
    for (int w = 0; w < 8; ++w) {
        int t8 = wtot_i[w];
        if (w < wid) base += t8;
        nact += t8;
    }
    int pos = base + (inc - cnt);
    #pragma unroll
    for (int j = 0; j < 4; ++j) {
        if ((mvbits >> j) & 1) midx_s[pos++] = (tid << 2) + j;
    }

    const int ntiles = (nact + TM - 1) >> 5;
    const int nlast  = nact - 1;

    if (tid < 64) {
        pool_s[tid] = 0.f;
        wl_s[tid]   = w_last[h * QMID + tid];
        bb_s[tid]   = b_basic[h * QMID + tid];
    }
    for (int i = tid; i < QC; i += NTHREADS) red_s[i] = qp[i];
    __syncthreads();   // midx ready for staging; q staged

    // group decomposition
    const int g   = tid >> 7;         // 0 or 1
    const int gt  = tid & 127;        // thread within group
    const int rg  = gt >> 4;          // 0..7 -> rows rg*4..rg*4+3
    const int cg  = gt & 15;          // 0..15 -> cols cg*4..cg*4+3
    const uint32_t mybuf_addr = smem_u32(g ? kf1_s : kf0_s);
    const float*   mybuf      = g ? kf1_s : kf0_s;
    const int      barid      = 1 + g;

    // stage one gathered 32-row tile (clamped index for pad rows)
    // 1024 float4 per tile / 128 threads = 8 iters; swizzle key (m>>2)&7
    #define STAGE_TILE_G(TILE)                                                     \
        {                                                                          \
            const int _t0 = (TILE) * TM;                                           \
            _Pragma("unroll")                                                      \
            for (int _it = 0; _it < 8; ++_it) {                                    \
                int _f  = gt + _it * 128;                                          \
                int _m  = _f >> 5;                                                 \
                int _qk = _f & 31;                                                 \
                int _qs = _qk ^ ((_m >> 2) & 7);                                   \
                int _sl = _t0 + _m; if (_sl > nlast) _sl = nlast;                  \
                int _src_row = midx_s[_sl];                                        \
                cp_async16(mybuf_addr + (uint32_t)(((_m << 7) + (_qs << 2)) << 2), \
                           kfp + ((size_t)_src_row << 7) + (_qk << 2));            \
            }                                                                      \
            CP_COMMIT();                                                           \
        }

    // each group prefetches its first tile (overlaps wq build)
    if (g < ntiles) STAGE_TILE_G(g);

    // wq[k][o] = q[k] * w_basic[h][k][o]
    for (int i = tid; i < QC * QMID; i += NTHREADS) {
        int k = i >> 6;
        wq_s[i] = red_s[k] * w_basic[(h * QC + k) * QMID + (i & 63)];
    }
    __syncthreads();   // wq ready

    float bb4[4], wl4[4];
    #pragma unroll
    for (int j = 0; j < 4; ++j) {
        bb4[j] = bb_s[(cg << 2) + j];
        wl4[j] = wl_s[(cg << 2) + j];
    }
    float pp[4] = {0.f, 0.f, 0.f, 0.f};
    float se_p  = 0.f;

    const float* wb  = wq_s + (cg << 2);
    const float* kfb = mybuf + (rg << 9);     // rg*4 rows * 128

    // ---------------- main tiles: group g handles tiles g, g+2, ... ----------
    for (int tile = g; tile < ntiles; tile += 2) {
        CP_WAIT0();
        BAR_GROUP(barid);

        // full-k GEMM: 4 rows x 4 cols per thread, 32 k-quads
        unsigned long long acc[4][2];
        #pragma unroll
        for (int r = 0; r < 4; ++r) { acc[r][0] = 0ULL; acc[r][1] = 0ULL; }

        #pragma unroll 4
        for (int qq = 0; qq < 32; ++qq) {
            const int qs4 = ((qq ^ rg) << 2);
            float4 a[4];
            #pragma unroll
            for (int r = 0; r < 4; ++r)
                a[r] = *(const float4*)(kfb + (r << 7) + qs4);

            ulonglong2 bv[4];
            #pragma unroll
            for (int j = 0; j < 4; ++j)
                bv[j] = *(const ulonglong2*)(wb + ((qq << 2) + j) * QMID);

            #pragma unroll
            for (int j = 0; j < 4; ++j) {
                #pragma unroll
                for (int r = 0; r < 4; ++r) {
                    float av = (j == 0) ? a[r].x : (j == 1) ? a[r].y : (j == 2) ? a[r].z : a[r].w;
                    unsigned long long ap = splat2(av);
                    ffma2(acc[r][0], ap, bv[j].x);
                    ffma2(acc[r][1], ap, bv[j].y);
                }
            }
        }

        BAR_GROUP(barid);   // group's reads of its buffer done

        // issue staging for this group's next tile (overlaps epilogue)
        if (tile + 2 < ntiles) STAGE_TILE_G(tile + 2);

        // register epilogue: relu+bias, pool, logit -> e (no-max softmax)
        #pragma unroll
        for (int r = 0; r < 4; ++r) {
            const int mg = tile * TM + (rg << 2) + r;
            const float vld = (mg < nact) ? 1.f : 0.f;
            float2 lo = unpack2(acc[r][0]);
            float2 hi = unpack2(acc[r][1]);
            float x0 = fmaxf(lo.x + bb4[0], 0.f);
            float x1 = fmaxf(lo.y + bb4[1], 0.f);
            float x2 = fmaxf(hi.x + bb4[2], 0.f);
            float x3 = fmaxf(hi.y + bb4[3], 0.f);
            pp[0] += x0 * vld; pp[1] += x1 * vld; pp[2] += x2 * vld; pp[3] += x3 * vld;
            float lp = x0 * wl4[0] + x1 * wl4[1] + x2 * wl4[2] + x3 * wl4[3];
            lp += __shfl_xor_sync(~0u, lp, 1);
            lp += __shfl_xor_sync(~0u, lp, 2);
            lp += __shfl_xor_sync(~0u, lp, 4);
            lp += __shfl_xor_sync(~0u, lp, 8);
            float e = __expf(lp) * vld;
            if (cg == 0) { if (mg < nact) logit_s[mg] = e; se_p += e; }
        }
    }

    // ---------------- reductions: pool + se ----------------
    #pragma unroll
    for (int j = 0; j < 4; ++j) {
        float v = pp[j];
        v += __shfl_xor_sync(~0u, v, 16);
        if (lid < 16) atomicAdd(&pool_s[(cg << 2) + j], v);
    }
    {
        float v = se_p;   // nonzero only on cg==0 lanes (lid 0 and 16)
        v += __shfl_xor_sync(~0u, v, 16);
        if (lid == 0) sc_s[wid] = v;
    }
    __syncthreads();   // e values + pool + se partials complete
    if (tid == 0) {
        float v = 0.f;
        #pragma unroll
        for (int w = 0; w < 8; ++w) v += sc_s[w];
        sc_s[33] = 1.0f / v;
    }
    __syncthreads();
    const float inv_se  = sc_s[33];
    const float cnt_inv = 1.0f / (float)nact;

    // ---------------- v2 = alpha^T @ value2 over ACTIVE rows only ------------
    {
        const int qc    = tid & 31;
        const int slice = tid >> 5;
        const float* vbase = value2 + (size_t)bh * QM * QC + (qc << 2);
        float ax = 0.f, ay = 0.f, az = 0.f, aw = 0.f;
        #pragma unroll 8
        for (int i = slice; i < nact; i += 8) {
            float a4 = logit_s[i];
            int msrc = midx_s[i];
            float4 v = __ldcs((const float4*)(vbase + ((size_t)msrc << 7)));
            ax += a4 * v.x; ay += a4 * v.y; az += a4 * v.z; aw += a4 * v.w;
        }
        *(float4*)(wq_s + slice * QC + (qc << 2)) = make_float4(ax, ay, az, aw);
    }
    __syncthreads();

    // ---------------- final reduce + channel gate + output ----------------
    if (tid < QC) {
        const int d = tid;
        float v2v = 0.f;
        #pragma unroll
        for (int s = 0; s < 8; ++s) v2v += wq_s[s * QC + d];
        v2v *= inv_se;

        const float* w2 = w_last2 + (h * QMID) * QC + d;
        float pv = 0.f;
        #pragma unroll 8
        for (int o = 0; o < QMID; ++o) pv += (pool_s[o] * cnt_inv) * w2[o * QC];
        float z   = pv + b_last2[h * QC + d];
        float acv = 1.0f / (1.0f + __expf(-z));
        out[bh * QC + d] = value1[bh * QC + d] * v2v * acv;
    }
}

extern "C" void kernel_launch(void* const* d_in, const int* in_sizes, int n_in,
                              void* d_out, int out_size) {
    const float* query    = (const float*)d_in[0];
    const float* key_feat = (const float*)d_in[1];
    const int*   att_mask = (const int*)  d_in[2];
    const float* value1   = (const float*)d_in[3];
    const float* value2   = (const float*)d_in[4];
    const float* w_basic  = (const float*)d_in[5];
    const float* b_basic  = (const float*)d_in[6];
    const float* w_last   = (const float*)d_in[7];
    const float* b_last   = (const float*)d_in[8];
    const float* w_last2  = (const float*)d_in[9];
    const float* b_last2  = (const float*)d_in[10];
    float* out = (float*)d_out;

    const int smem_bytes = SMEM_FLOATS * (int)sizeof(float);
    cudaFuncSetAttribute(scatt_kernel, cudaFuncAttributeMaxDynamicSharedMemorySize, smem_bytes);
    scatt_kernel<<<QB * QH, NTHREADS, smem_bytes>>>(
        query, key_feat, att_mask, value1, value2,
        w_basic, b_basic, w_last, b_last, w_last2, b_last2, out);
}